// round 9
// baseline (speedup 1.0000x reference)
#include <cuda_runtime.h>
#include <cuda_bf16.h>
#include <stdint.h>
#include <math.h>

// ---------------- problem constants ----------------
#define NNODES 50000
#define NEDGES 800000
#define NGRAPH 8
#define NPG    6250
#define CIN    512
#define HID    256
#define H3     768
#define KTOP   5000
#define CAP    96
#define NCHUNK 25
#define RSLICE 25

// ---------------- device scratch ----------------
__device__ __align__(256) float g_xw [NNODES * HID];
__device__ __align__(256) float g_x1 [NNODES * HID];
__device__ __align__(256) float g_x2 [NNODES * HID];
__device__ __align__(256) float g_x3 [NNODES * HID];
__device__ __align__(256) float g_deg[NNODES];
__device__ __align__(256) int   g_cnt[NNODES];
__device__ __align__(256) int   g_eperm[NNODES * CAP];
__device__ __align__(256) int   g_src [NEDGES];
__device__ __align__(256) float g_norm[NEDGES];
__device__ __align__(256) float g_sp  [3 * NNODES];
__device__ __align__(256) float g_score[NNODES];
__device__ __align__(256) float g_sel  [NNODES];
__device__ unsigned g_thr[NGRAPH];
__device__ int      g_needeq[NGRAPH];
__device__ int g_eqcnt[NGRAPH * NCHUNK];
__device__ int g_eqoff[NGRAPH * NCHUNK];
__device__ __align__(256) float g_rsum[NGRAPH * 3 * RSLICE * HID];
__device__ __align__(256) float g_rmax[NGRAPH * 3 * RSLICE * HID];
__device__ __align__(256) float g_readout[NGRAPH * 2 * H3];
__device__ float g_pwinv;
// bf16 hi/lo splits
__device__ __align__(256) __nv_bfloat16 g_w1h[CIN * HID];
__device__ __align__(256) __nv_bfloat16 g_w1l[CIN * HID];
__device__ __align__(256) __nv_bfloat16 g_w2h[HID * HID];
__device__ __align__(256) __nv_bfloat16 g_w2l[HID * HID];
__device__ __align__(256) __nv_bfloat16 g_xh [NNODES * CIN];
__device__ __align__(256) __nv_bfloat16 g_xl [NNODES * CIN];
__device__ __align__(256) __nv_bfloat16 g_x1h[NNODES * HID];
__device__ __align__(256) __nv_bfloat16 g_x1l[NNODES * HID];
__device__ __align__(256) __nv_bfloat16 g_x2h[NNODES * HID];
__device__ __align__(256) __nv_bfloat16 g_x2l[NNODES * HID];

__device__ __forceinline__ float* buf_select(int sel) {
    switch (sel) {
        case 0:  return g_xw;
        case 1:  return g_x1;
        case 2:  return g_x2;
        default: return g_x3;
    }
}

// ---------------- setup ----------------
__global__ void zero_kernel() {
    int i = blockIdx.x * 256 + threadIdx.x;
    if (i < NNODES) { g_deg[i] = 0.f; g_cnt[i] = 0; }
}

__global__ void fill_kernel(const int* __restrict__ ei,
                            const float* __restrict__ ea) {
    int e = blockIdx.x * 256 + threadIdx.x;
    if (e >= NEDGES) return;
    int s = ei[e];
    int d = ei[NEDGES + e];
    if ((unsigned)s >= NNODES || (unsigned)d >= NNODES) { g_src[e] = 0; return; }
    g_src[e] = s;
    atomicAdd(&g_deg[d], ea[e]);
    int slot = atomicAdd(&g_cnt[d], 1);
    if (slot < CAP) g_eperm[d * CAP + slot] = e;
}

__global__ void dinv_kernel() {
    int i = blockIdx.x * 256 + threadIdx.x;
    if (i < NNODES) g_deg[i] = rsqrtf(g_deg[i] + 1.0f);
}

__global__ void norm_kernel(const int* __restrict__ ei,
                            const float* __restrict__ ea) {
    int e = blockIdx.x * 256 + threadIdx.x;
    if (e >= NEDGES) return;
    int d = ei[NEDGES + e];
    if ((unsigned)d >= NNODES) { g_norm[e] = 0.f; return; }
    g_norm[e] = g_deg[g_src[e]] * ea[e] * g_deg[d];
}

__global__ void splitw_kernel(const float* __restrict__ W, int n, int which) {
    int i = blockIdx.x * 256 + threadIdx.x;
    if (i >= n) return;
    __nv_bfloat16* hi = (which == 0) ? g_w1h : g_w2h;
    __nv_bfloat16* lo = (which == 0) ? g_w1l : g_w2l;
    float w = W[i];
    __nv_bfloat16 h = __float2bfloat16(w);
    hi[i] = h;
    lo[i] = __float2bfloat16(w - __bfloat162float(h));
}

// split input x (vectorized, 4 elems/thread)
__global__ void splitx_kernel(const float* __restrict__ X) {
    int i = blockIdx.x * 256 + threadIdx.x;           // quad index
    const int nq = NNODES * CIN / 4;
    if (i >= nq) return;
    float4 v = *(const float4*)(X + (size_t)i * 4);
    float f[4] = {v.x, v.y, v.z, v.w};
    __nv_bfloat16 h[4], l[4];
#pragma unroll
    for (int j = 0; j < 4; j++) {
        h[j] = __float2bfloat16(f[j]);
        l[j] = __float2bfloat16(f[j] - __bfloat162float(h[j]));
    }
    *(uint2*)(g_xh + (size_t)i * 4) = *(uint2*)h;
    *(uint2*)(g_xl + (size_t)i * 4) = *(uint2*)l;
}

// ---------------- bf16x3 tensor-core GEMM (cp.async pipelined) ----------------
#define GBM 128
#define GBN 128
#define GBK 32
#define AKP 40     // A smem row stride (bf16)
#define BNP 136    // B smem row stride (bf16)
// stage layout (bytes)
#define AH_OFF 0
#define AL_OFF 10240
#define BH_OFF 20480
#define BL_OFF 29184
#define STAGE  37888

__device__ __forceinline__ uint32_t s2u(const void* p) {
    uint32_t a;
    asm("{ .reg .u64 t; cvta.to.shared.u64 t, %1; cvt.u32.u64 %0, t; }"
        : "=r"(a) : "l"(p));
    return a;
}
__device__ __forceinline__ void cp16(uint32_t dst, const void* src, bool ok) {
    asm volatile("cp.async.cg.shared.global [%0], [%1], 16, %2;\n"
                 :: "r"(dst), "l"(src), "r"(ok ? 16 : 0));
}
__device__ __forceinline__ void cp_commit() {
    asm volatile("cp.async.commit_group;\n");
}
__device__ __forceinline__ void cp_wait0() {
    asm volatile("cp.async.wait_group 0;\n");
}
__device__ __forceinline__ void ldsm_x4(unsigned* r, uint32_t addr) {
    asm volatile("ldmatrix.sync.aligned.m8n8.x4.shared.b16 {%0,%1,%2,%3}, [%4];"
                 : "=r"(r[0]), "=r"(r[1]), "=r"(r[2]), "=r"(r[3]) : "r"(addr));
}
__device__ __forceinline__ void ldsm_x4_t(unsigned* r, uint32_t addr) {
    asm volatile("ldmatrix.sync.aligned.m8n8.x4.trans.shared.b16 {%0,%1,%2,%3}, [%4];"
                 : "=r"(r[0]), "=r"(r[1]), "=r"(r[2]), "=r"(r[3]) : "r"(addr));
}
__device__ __forceinline__ void mma_bf16(float* d, const unsigned* a, const unsigned* b) {
    asm volatile(
        "mma.sync.aligned.m16n8k16.row.col.f32.bf16.bf16.f32 "
        "{%0,%1,%2,%3}, {%4,%5,%6,%7}, {%8,%9}, {%0,%1,%2,%3};\n"
        : "+f"(d[0]), "+f"(d[1]), "+f"(d[2]), "+f"(d[3])
        : "r"(a[0]), "r"(a[1]), "r"(a[2]), "r"(a[3]), "r"(b[0]), "r"(b[1]));
}

// asrc: 0 -> (g_xh,g_xl); 1 -> (g_x1h,g_x1l); 2 -> (g_x2h,g_x2l)
__global__ __launch_bounds__(256) void bgemm_kernel(int asrc, int wsel, int K)
{
    const __nv_bfloat16* Ah = (asrc == 0) ? g_xh : ((asrc == 1) ? g_x1h : g_x2h);
    const __nv_bfloat16* Al = (asrc == 0) ? g_xl : ((asrc == 1) ? g_x1l : g_x2l);
    const __nv_bfloat16* Bh = (wsel == 0) ? g_w1h : g_w2h;
    const __nv_bfloat16* Bl = (wsel == 0) ? g_w1l : g_w2l;
    float* C = g_xw;

    extern __shared__ char smem[];
    const uint32_t sbase = s2u(smem);

    const int tid = threadIdx.x;
    const int bm = blockIdx.y * GBM;
    const int bn = blockIdx.x * GBN;

    const int lane = tid & 31;
    const int warp = tid >> 5;
    const int wm = warp >> 1;
    const int wn = warp & 1;
    const int lrow = lane >> 2;
    const int lq   = lane & 3;
    const int la = lane & 15, ha = lane >> 4;

    // loader assignments
    const int a_row = tid >> 1;                 // 0..127
    const int a_c0  = (tid & 1) * 16;           // 0 or 16
    const bool a_ok = (bm + a_row) < NNODES;
    const int a_grow = a_ok ? (bm + a_row) : (NNODES - 1);
    const int b_k  = tid >> 3;                  // 0..31
    const int b_n0 = (tid & 7) * 16;            // 0..112

    float d[2][8][4];
#pragma unroll
    for (int i = 0; i < 2; i++)
#pragma unroll
        for (int j = 0; j < 8; j++)
#pragma unroll
            for (int r = 0; r < 4; r++) d[i][j][r] = 0.f;

    const int T = K / GBK;

    // tile loader
    auto load_tile = [&](int t, int s) {
        uint32_t st = sbase + s * STAGE;
        const __nv_bfloat16* pah = Ah + (size_t)a_grow * K + t * GBK + a_c0;
        const __nv_bfloat16* pal = Al + (size_t)a_grow * K + t * GBK + a_c0;
        uint32_t da = st + AH_OFF + (uint32_t)(a_row * AKP + a_c0) * 2;
        cp16(da,     pah,     a_ok);
        cp16(da + 16, pah + 8, a_ok);
        da = st + AL_OFF + (uint32_t)(a_row * AKP + a_c0) * 2;
        cp16(da,     pal,     a_ok);
        cp16(da + 16, pal + 8, a_ok);
        const __nv_bfloat16* pbh = Bh + (size_t)(t * GBK + b_k) * HID + bn + b_n0;
        const __nv_bfloat16* pbl = Bl + (size_t)(t * GBK + b_k) * HID + bn + b_n0;
        uint32_t db = st + BH_OFF + (uint32_t)(b_k * BNP + b_n0) * 2;
        cp16(db,     pbh,     true);
        cp16(db + 16, pbh + 8, true);
        db = st + BL_OFF + (uint32_t)(b_k * BNP + b_n0) * 2;
        cp16(db,     pbl,     true);
        cp16(db + 16, pbl + 8, true);
    };

    load_tile(0, 0);
    cp_commit();

    int buf = 0;
    for (int t = 0; t < T; t++) {
        cp_wait0();
        __syncthreads();
        if (t + 1 < T) { load_tile(t + 1, buf ^ 1); cp_commit(); }

        const uint32_t st = sbase + buf * STAGE;
        const uint32_t ash0 = st + AH_OFF;
        const uint32_t asl0 = st + AL_OFF;
        const uint32_t bsh0 = st + BH_OFF;
        const uint32_t bsl0 = st + BL_OFF;
#pragma unroll
        for (int ks = 0; ks < GBK; ks += 16) {
            unsigned ah[2][4], al[2][4];
#pragma unroll
            for (int fm = 0; fm < 2; fm++) {
                int m = wm * 32 + fm * 16 + la;
                int kc = ks + ha * 8;
                uint32_t off = (uint32_t)(m * AKP + kc) * 2;
                ldsm_x4(ah[fm], ash0 + off);
                ldsm_x4(al[fm], asl0 + off);
            }
#pragma unroll
            for (int fp = 0; fp < 4; fp++) {
                unsigned bh[4], bl[4];
                int kr = ks + la;
                int nc = wn * 64 + fp * 16 + ha * 8;
                uint32_t off = (uint32_t)(kr * BNP + nc) * 2;
                ldsm_x4_t(bh, bsh0 + off);
                ldsm_x4_t(bl, bsl0 + off);
#pragma unroll
                for (int fm = 0; fm < 2; fm++) {
#pragma unroll
                    for (int tt = 0; tt < 2; tt++) {
                        float* acc = d[fm][fp * 2 + tt];
                        mma_bf16(acc, ah[fm], &bh[tt * 2]);
                        mma_bf16(acc, ah[fm], &bl[tt * 2]);
                        mma_bf16(acc, al[fm], &bh[tt * 2]);
                    }
                }
            }
        }
        buf ^= 1;
    }

    // ---- epilogue ----
#pragma unroll
    for (int fm = 0; fm < 2; fm++) {
#pragma unroll
        for (int fn = 0; fn < 8; fn++) {
            int row = bm + wm * 32 + fm * 16 + lrow;
            int col = bn + wn * 64 + fn * 8 + 2 * lq;
            if (row < NNODES)
                *(float2*)&C[(size_t)row * HID + col] =
                    make_float2(d[fm][fn][0], d[fm][fn][1]);
            if (row + 8 < NNODES)
                *(float2*)&C[(size_t)(row + 8) * HID + col] =
                    make_float2(d[fm][fn][2], d[fm][fn][3]);
        }
    }
}

// ---------------- GCN aggregation + fused score + bf16 split out ----------------
__global__ __launch_bounds__(256) void agg_kernel(
    const float* __restrict__ bias, int out_sel,
    const float* __restrict__ pwseg, int layer, int write_split)
{
    const float* xw = g_xw;
    float* out = buf_select(out_sel);
    const int node = blockIdx.x;
    const int t = threadIdx.x;
    __shared__ int   s_src[CAP];
    __shared__ float s_nrm[CAP];
    __shared__ int   s_cnt;
    __shared__ float s_wsum[8];
    if (t == 0) { int c = g_cnt[node]; s_cnt = c < CAP ? c : CAP; }
    __syncthreads();
    const int cnt = s_cnt;
    if (t < cnt) {
        int e = g_eperm[node * CAP + t];
        s_src[t] = g_src[e];
        s_nrm[t] = g_norm[e];
    }
    __syncthreads();

    float d = g_deg[node];
    float acc = d * d * xw[(size_t)node * HID + t] + bias[t];
    int j = 0;
    for (; j + 4 <= cnt; j += 4) {
        float v0 = xw[(size_t)s_src[j + 0] * HID + t];
        float v1 = xw[(size_t)s_src[j + 1] * HID + t];
        float v2 = xw[(size_t)s_src[j + 2] * HID + t];
        float v3 = xw[(size_t)s_src[j + 3] * HID + t];
        acc += s_nrm[j + 0] * v0;
        acc += s_nrm[j + 1] * v1;
        acc += s_nrm[j + 2] * v2;
        acc += s_nrm[j + 3] * v3;
    }
    for (; j < cnt; j++)
        acc += s_nrm[j] * xw[(size_t)s_src[j] * HID + t];

    float v = fmaxf(acc, 0.f);
    out[(size_t)node * HID + t] = v;

    if (write_split) {
        __nv_bfloat16* oh = (out_sel == 1) ? g_x1h : g_x2h;
        __nv_bfloat16* ol = (out_sel == 1) ? g_x1l : g_x2l;
        __nv_bfloat16 h = __float2bfloat16(v);
        oh[(size_t)node * HID + t] = h;
        ol[(size_t)node * HID + t] = __float2bfloat16(v - __bfloat162float(h));
    }

    float p = v * pwseg[t];
#pragma unroll
    for (int o = 16; o > 0; o >>= 1) p += __shfl_xor_sync(0xffffffffu, p, o);
    if ((t & 31) == 0) s_wsum[t >> 5] = p;
    __syncthreads();
    if (t == 0) {
        float s = 0.f;
#pragma unroll
        for (int w = 0; w < 8; w++) s += s_wsum[w];
        g_sp[layer * NNODES + node] = s;
    }
}

// ---------------- scoring ----------------
__global__ void pwnorm_kernel(const float* __restrict__ pw) {
    __shared__ float red[256];
    float s = 0.f;
    for (int i = threadIdx.x; i < H3; i += 256) s += pw[i] * pw[i];
    red[threadIdx.x] = s;
    __syncthreads();
    for (int o = 128; o > 0; o >>= 1) {
        if (threadIdx.x < o) red[threadIdx.x] += red[threadIdx.x + o];
        __syncthreads();
    }
    if (threadIdx.x == 0) g_pwinv = rsqrtf(red[0]);
}

__global__ void scorefin_kernel() {
    int i = blockIdx.x * 256 + threadIdx.x;
    if (i >= NNODES) return;
    float dot = g_sp[i] + g_sp[NNODES + i] + g_sp[2 * NNODES + i];
    g_score[i] = 1.f / (1.f + expf(-dot * g_pwinv));
}

// ---------------- exact top-K threshold per graph ----------------
__global__ void radix_kernel() {
    const int g = blockIdx.x;
    const float* sc = g_score + g * NPG;
    __shared__ int hist[256];
    __shared__ unsigned s_prefix;
    __shared__ int s_remaining;
    if (threadIdx.x == 0) { s_prefix = 0u; s_remaining = KTOP; }
    __syncthreads();
    for (int pass = 3; pass >= 0; --pass) {
        hist[threadIdx.x] = 0;
        __syncthreads();
        unsigned prefix = s_prefix;
        int shift = pass * 8;
        for (int i = threadIdx.x; i < NPG; i += 256) {
            unsigned bits = __float_as_uint(sc[i]);
            bool match = (pass == 3) || ((bits >> (shift + 8)) == prefix);
            if (match) atomicAdd(&hist[(bits >> shift) & 255u], 1);
        }
        __syncthreads();
        if (threadIdx.x == 0) {
            int rem = s_remaining;
            unsigned p = s_prefix;
            for (int b = 255; b >= 0; --b) {
                if (hist[b] >= rem) { s_prefix = (p << 8) | (unsigned)b; break; }
                rem -= hist[b];
            }
            s_remaining = rem;
        }
        __syncthreads();
    }
    if (threadIdx.x == 0) { g_thr[g] = s_prefix; g_needeq[g] = s_remaining; }
}

// ---- stable tie resolution ----
__global__ void eqcnt_kernel() {
    const int ch = blockIdx.x % NCHUNK;
    const int g  = blockIdx.x / NCHUNK;
    const unsigned thr = g_thr[g];
    int i = ch * 256 + threadIdx.x;
    bool eq = (i < NPG) && (__float_as_uint(g_score[g * NPG + i]) == thr);
    unsigned bal = __ballot_sync(0xffffffffu, eq);
    __shared__ int wcnt[8];
    if ((threadIdx.x & 31) == 0) wcnt[threadIdx.x >> 5] = __popc(bal);
    __syncthreads();
    if (threadIdx.x == 0) {
        int s = 0;
#pragma unroll
        for (int w = 0; w < 8; w++) s += wcnt[w];
        g_eqcnt[g * NCHUNK + ch] = s;
    }
}

__global__ void eqscan_kernel() {
    const int g = blockIdx.x;
    if (threadIdx.x == 0) {
        int run = 0;
        for (int c = 0; c < NCHUNK; c++) {
            g_eqoff[g * NCHUNK + c] = run;
            run += g_eqcnt[g * NCHUNK + c];
        }
    }
}

__global__ void mark_kernel() {
    const int ch = blockIdx.x % NCHUNK;
    const int g  = blockIdx.x / NCHUNK;
    const unsigned thr = g_thr[g];
    const int need = g_needeq[g];
    int i = ch * 256 + threadIdx.x;
    float s = 0.f; unsigned bits = 0u;
    if (i < NPG) { s = g_score[g * NPG + i]; bits = __float_as_uint(s); }
    bool eq = (i < NPG) && (bits == thr);
    unsigned bal = __ballot_sync(0xffffffffu, eq);
    int lane = threadIdx.x & 31, warp = threadIdx.x >> 5;
    int lr = __popc(bal & ((1u << lane) - 1u));
    __shared__ int wcnt[8], woff[8];
    if (lane == 0) wcnt[warp] = __popc(bal);
    __syncthreads();
    if (threadIdx.x == 0) {
        int run = 0;
#pragma unroll
        for (int w = 0; w < 8; w++) { woff[w] = run; run += wcnt[w]; }
    }
    __syncthreads();
    if (i < NPG) {
        float out = 0.f;
        if (bits > thr) out = s;
        else if (eq) {
            int rank = g_eqoff[g * NCHUNK + ch] + woff[warp] + lr;
            if (rank < need) out = s;
        }
        g_sel[g * NPG + i] = out;
    }
}

// ---------------- readout, 2-stage ----------------
__global__ __launch_bounds__(256) void readout1_kernel() {
    const int sl = blockIdx.x % RSLICE;
    const int c  = (blockIdx.x / RSLICE) % 3;
    const int g  = blockIdx.x / (RSLICE * 3);
    const float* X = (c == 0) ? g_x1 : ((c == 1) ? g_x2 : g_x3);
    const int f = threadIdx.x;
    const float* sel = g_sel + g * NPG;
    const size_t rowbase = (size_t)g * NPG * HID;
    const int n0 = sl * (NPG / RSLICE), n1 = n0 + NPG / RSLICE;
    float sum0 = 0.f, sum1 = 0.f, mx = 0.f;
    for (int i = n0; i < n1; i += 2) {
        float v0 = sel[i]     * X[rowbase + (size_t)i * HID + f];
        float v1 = sel[i + 1] * X[rowbase + (size_t)(i + 1) * HID + f];
        sum0 += v0; sum1 += v1;
        mx = fmaxf(mx, fmaxf(v0, v1));
    }
    g_rsum[(size_t)blockIdx.x * HID + f] = sum0 + sum1;
    g_rmax[(size_t)blockIdx.x * HID + f] = mx;
}

__global__ __launch_bounds__(256) void readout2_kernel() {
    const int c = blockIdx.x % 3, g = blockIdx.x / 3;
    const int f = threadIdx.x;
    const int base = (g * 3 + c) * RSLICE;
    float sum = 0.f, mx = 0.f;
    for (int k = 0; k < RSLICE; k++) {
        sum += g_rsum[(size_t)(base + k) * HID + f];
        mx = fmaxf(mx, g_rmax[(size_t)(base + k) * HID + f]);
    }
    g_readout[g * 2 * H3 + c * HID + f]      = sum * (1.f / (float)KTOP);
    g_readout[g * 2 * H3 + H3 + c * HID + f] = mx;
}

// ---------------- final MLP ----------------
__global__ __launch_bounds__(256) void mlp_kernel(
    const float* __restrict__ lw1, const float* __restrict__ lb1,
    const float* __restrict__ lw2, const float* __restrict__ lb2,
    const float* __restrict__ lw3, const float* __restrict__ lb3,
    float* __restrict__ out)
{
    const int g = blockIdx.x, t = threadIdx.x;
    __shared__ float r[2 * H3];
    __shared__ float h1[HID];
    __shared__ float h2[HID / 2];
    for (int i = t; i < 2 * H3; i += 256) r[i] = g_readout[g * 2 * H3 + i];
    __syncthreads();
    {
        float a0 = 0.f, a1 = 0.f, a2 = 0.f, a3 = 0.f;
        for (int k = 0; k < 2 * H3; k += 4) {
            a0 += r[k + 0] * lw1[(size_t)(k + 0) * HID + t];
            a1 += r[k + 1] * lw1[(size_t)(k + 1) * HID + t];
            a2 += r[k + 2] * lw1[(size_t)(k + 2) * HID + t];
            a3 += r[k + 3] * lw1[(size_t)(k + 3) * HID + t];
        }
        h1[t] = fmaxf((a0 + a1) + (a2 + a3) + lb1[t], 0.f);
    }
    __syncthreads();
    if (t < 128) {
        float a0 = 0.f, a1 = 0.f;
        for (int k = 0; k < HID; k += 2) {
            a0 += h1[k + 0] * lw2[(size_t)(k + 0) * 128 + t];
            a1 += h1[k + 1] * lw2[(size_t)(k + 1) * 128 + t];
        }
        h2[t] = fmaxf(a0 + a1 + lb2[t], 0.f);
    }
    __syncthreads();
    if (t < 3) {
        float a = lb3[t];
        for (int k = 0; k < 128; k++) a += h2[k] * lw3[k * 3 + t];
        out[g * 3 + t] = a;
    }
}

// ---------------- launch ----------------
extern "C" void kernel_launch(void* const* d_in, const int* in_sizes, int n_in,
                              void* d_out, int out_size)
{
    int ix = -1, iei = -1, iea = -1, iW1 = -1, iW2 = -1, ipw = -1;
    int ilw1 = -1, ilw2 = -1, ilb2 = -1, ilw3 = -1, ilb3 = -1;
    int b256[3] = {-1, -1, -1};
    int nb = 0;
    for (int i = 0; i < n_in; i++) {
        switch (in_sizes[i]) {
            case 25600000: ix   = i; break;
            case 1600000:  iei  = i; break;
            case 800000:   iea  = i; break;
            case 131072:   iW1  = i; break;
            case 65536:    iW2  = i; break;
            case 768:      ipw  = i; break;
            case 393216:   ilw1 = i; break;
            case 32768:    ilw2 = i; break;
            case 128:      ilb2 = i; break;
            case 384:      ilw3 = i; break;
            case 3:        ilb3 = i; break;
            case 256:      if (nb < 3) b256[nb++] = i; break;
            default: break;
        }
    }

    const float* x   = (const float*)d_in[ix];
    const int*   ei  = (const int*)d_in[iei];
    const float* ea  = (const float*)d_in[iea];
    const float* W1  = (const float*)d_in[iW1];
    const float* b1  = (const float*)d_in[b256[0]];
    const float* W2  = (const float*)d_in[iW2];
    const float* b2  = (const float*)d_in[b256[1]];
    const float* pw  = (const float*)d_in[ipw];
    const float* lw1 = (const float*)d_in[ilw1];
    const float* lb1 = (const float*)d_in[b256[2]];
    const float* lw2 = (const float*)d_in[ilw2];
    const float* lb2 = (const float*)d_in[ilb2];
    const float* lw3 = (const float*)d_in[ilw3];
    const float* lb3 = (const float*)d_in[ilb3];
    float* out = (float*)d_out;

    static int smem_set = 0;
    if (!smem_set) {
        cudaFuncSetAttribute(bgemm_kernel,
                             cudaFuncAttributeMaxDynamicSharedMemorySize,
                             2 * STAGE);
        smem_set = 1;
    }

    const int nb_nodes = (NNODES + 255) / 256;
    const int nb_edges = (NEDGES + 255) / 256;
    dim3 gemm_grid(HID / GBN, (NNODES + GBM - 1) / GBM);

    // order chosen so launch #4 (ncu capture point) is the big GEMM
    splitw_kernel<<<(CIN * HID + 255) / 256, 256>>>(W1, CIN * HID, 0);      // 1
    splitx_kernel<<<(NNODES * CIN / 4 + 255) / 256, 256>>>(x);              // 2
    zero_kernel<<<nb_nodes, 256>>>();                                       // 3
    bgemm_kernel<<<gemm_grid, 256, 2 * STAGE>>>(0, 0, CIN);                 // 4
    splitw_kernel<<<(HID * HID + 255) / 256, 256>>>(W2, HID * HID, 1);      // 5
    fill_kernel<<<nb_edges, 256>>>(ei, ea);                                 // 6
    dinv_kernel<<<nb_nodes, 256>>>();                                       // 7
    norm_kernel<<<nb_edges, 256>>>(ei, ea);                                 // 8

    agg_kernel<<<NNODES, 256>>>(b1, 1, pw, 0, 1);                           // 9
    bgemm_kernel<<<gemm_grid, 256, 2 * STAGE>>>(1, 1, HID);                 // 10
    agg_kernel<<<NNODES, 256>>>(b2, 2, pw + HID, 1, 1);                     // 11
    bgemm_kernel<<<gemm_grid, 256, 2 * STAGE>>>(2, 1, HID);                 // 12
    agg_kernel<<<NNODES, 256>>>(b2, 3, pw + 2 * HID, 2, 0);                 // 13

    pwnorm_kernel<<<1, 256>>>(pw);
    scorefin_kernel<<<nb_nodes, 256>>>();
    radix_kernel<<<NGRAPH, 256>>>();
    eqcnt_kernel<<<NGRAPH * NCHUNK, 256>>>();
    eqscan_kernel<<<NGRAPH, 32>>>();
    mark_kernel<<<NGRAPH * NCHUNK, 256>>>();
    readout1_kernel<<<NGRAPH * 3 * RSLICE, 256>>>();
    readout2_kernel<<<NGRAPH * 3, 256>>>();
    mlp_kernel<<<NGRAPH, 256>>>(lw1, lb1, lw2, lb2, lw3, lb3, out);
}

// round 10
// speedup vs baseline: 1.0643x; 1.0643x over previous
#include <cuda_runtime.h>
#include <cuda_bf16.h>
#include <stdint.h>
#include <math.h>

// ---------------- problem constants ----------------
#define NNODES 50000
#define NEDGES 800000
#define NGRAPH 8
#define NPG    6250
#define CIN    512
#define HID    256
#define H3     768
#define KTOP   5000
#define CAP    96
#define NCHUNK 25
#define RSLICE 25

// ---------------- device scratch ----------------
__device__ __align__(256) float g_xw [NNODES * HID];
__device__ __align__(256) float g_x1 [NNODES * HID];
__device__ __align__(256) float g_x2 [NNODES * HID];
__device__ __align__(256) float g_x3 [NNODES * HID];
__device__ __align__(256) float g_deg[NNODES];
__device__ __align__(256) int   g_cnt[NNODES];
__device__ __align__(256) int   g_eperm[NNODES * CAP];
__device__ __align__(256) int   g_src [NEDGES];
__device__ __align__(256) float g_norm[NEDGES];
__device__ __align__(256) float g_sp  [3 * NNODES];
__device__ __align__(256) float g_score[NNODES];
__device__ __align__(256) float g_sel  [NNODES];
__device__ unsigned g_thr[NGRAPH];
__device__ int      g_needeq[NGRAPH];
__device__ int g_eqcnt[NGRAPH * NCHUNK];
__device__ int g_eqoff[NGRAPH * NCHUNK];
__device__ __align__(256) float g_rsum[NGRAPH * 3 * RSLICE * HID];
__device__ __align__(256) float g_rmax[NGRAPH * 3 * RSLICE * HID];
__device__ __align__(256) float g_readout[NGRAPH * 2 * H3];
__device__ float g_pwinv;
// bf16 hi/lo splits
__device__ __align__(256) __nv_bfloat16 g_w1h[CIN * HID];
__device__ __align__(256) __nv_bfloat16 g_w1l[CIN * HID];
__device__ __align__(256) __nv_bfloat16 g_w2h[HID * HID];
__device__ __align__(256) __nv_bfloat16 g_w2l[HID * HID];
__device__ __align__(256) __nv_bfloat16 g_xh [NNODES * CIN];
__device__ __align__(256) __nv_bfloat16 g_xl [NNODES * CIN];
__device__ __align__(256) __nv_bfloat16 g_x1h[NNODES * HID];
__device__ __align__(256) __nv_bfloat16 g_x1l[NNODES * HID];
__device__ __align__(256) __nv_bfloat16 g_x2h[NNODES * HID];
__device__ __align__(256) __nv_bfloat16 g_x2l[NNODES * HID];

__device__ __forceinline__ float* buf_select(int sel) {
    switch (sel) {
        case 0:  return g_xw;
        case 1:  return g_x1;
        case 2:  return g_x2;
        default: return g_x3;
    }
}

// ---------------- setup ----------------
__global__ void zero_kernel() {
    int i = blockIdx.x * 256 + threadIdx.x;
    if (i < NNODES) { g_deg[i] = 0.f; g_cnt[i] = 0; }
}

__global__ void fill_kernel(const int* __restrict__ ei,
                            const float* __restrict__ ea) {
    int e = blockIdx.x * 256 + threadIdx.x;
    if (e >= NEDGES) return;
    int s = ei[e];
    int d = ei[NEDGES + e];
    if ((unsigned)s >= NNODES || (unsigned)d >= NNODES) { g_src[e] = 0; return; }
    g_src[e] = s;
    atomicAdd(&g_deg[d], ea[e]);
    int slot = atomicAdd(&g_cnt[d], 1);
    if (slot < CAP) g_eperm[d * CAP + slot] = e;
}

__global__ void dinv_kernel() {
    int i = blockIdx.x * 256 + threadIdx.x;
    if (i < NNODES) g_deg[i] = rsqrtf(g_deg[i] + 1.0f);
}

__global__ void norm_kernel(const int* __restrict__ ei,
                            const float* __restrict__ ea) {
    int e = blockIdx.x * 256 + threadIdx.x;
    if (e >= NEDGES) return;
    int d = ei[NEDGES + e];
    if ((unsigned)d >= NNODES) { g_norm[e] = 0.f; return; }
    g_norm[e] = g_deg[g_src[e]] * ea[e] * g_deg[d];
}

__global__ void splitw_kernel(const float* __restrict__ W, int n, int which) {
    int i = blockIdx.x * 256 + threadIdx.x;
    if (i >= n) return;
    __nv_bfloat16* hi = (which == 0) ? g_w1h : g_w2h;
    __nv_bfloat16* lo = (which == 0) ? g_w1l : g_w2l;
    float w = W[i];
    __nv_bfloat16 h = __float2bfloat16(w);
    hi[i] = h;
    lo[i] = __float2bfloat16(w - __bfloat162float(h));
}

// split input x (vectorized, 4 elems/thread)
__global__ void splitx_kernel(const float* __restrict__ X) {
    int i = blockIdx.x * 256 + threadIdx.x;           // quad index
    const int nq = NNODES * CIN / 4;
    if (i >= nq) return;
    float4 v = *(const float4*)(X + (size_t)i * 4);
    float f[4] = {v.x, v.y, v.z, v.w};
    __nv_bfloat16 h[4], l[4];
#pragma unroll
    for (int j = 0; j < 4; j++) {
        h[j] = __float2bfloat16(f[j]);
        l[j] = __float2bfloat16(f[j] - __bfloat162float(h[j]));
    }
    *(uint2*)(g_xh + (size_t)i * 4) = *(uint2*)h;
    *(uint2*)(g_xl + (size_t)i * 4) = *(uint2*)l;
}

// ---------------- bf16x3 tensor-core GEMM (cp.async pipelined) ----------------
#define GBM 128
#define GBN 128
#define GBK 32
#define AKP 40     // A smem row stride (bf16)
#define BNP 136    // B smem row stride (bf16)
// stage layout (bytes)
#define AH_OFF 0
#define AL_OFF 10240
#define BH_OFF 20480
#define BL_OFF 29184
#define STAGE  37888

__device__ __forceinline__ uint32_t s2u(const void* p) {
    uint32_t a;
    asm("{ .reg .u64 t; cvta.to.shared.u64 t, %1; cvt.u32.u64 %0, t; }"
        : "=r"(a) : "l"(p));
    return a;
}
__device__ __forceinline__ void cp16(uint32_t dst, const void* src, bool ok) {
    asm volatile("cp.async.cg.shared.global [%0], [%1], 16, %2;\n"
                 :: "r"(dst), "l"(src), "r"(ok ? 16 : 0));
}
__device__ __forceinline__ void cp_commit() {
    asm volatile("cp.async.commit_group;\n");
}
__device__ __forceinline__ void cp_wait0() {
    asm volatile("cp.async.wait_group 0;\n");
}
__device__ __forceinline__ void ldsm_x4(unsigned* r, uint32_t addr) {
    asm volatile("ldmatrix.sync.aligned.m8n8.x4.shared.b16 {%0,%1,%2,%3}, [%4];"
                 : "=r"(r[0]), "=r"(r[1]), "=r"(r[2]), "=r"(r[3]) : "r"(addr));
}
__device__ __forceinline__ void ldsm_x4_t(unsigned* r, uint32_t addr) {
    asm volatile("ldmatrix.sync.aligned.m8n8.x4.trans.shared.b16 {%0,%1,%2,%3}, [%4];"
                 : "=r"(r[0]), "=r"(r[1]), "=r"(r[2]), "=r"(r[3]) : "r"(addr));
}
__device__ __forceinline__ void mma_bf16(float* d, const unsigned* a, const unsigned* b) {
    asm volatile(
        "mma.sync.aligned.m16n8k16.row.col.f32.bf16.bf16.f32 "
        "{%0,%1,%2,%3}, {%4,%5,%6,%7}, {%8,%9}, {%0,%1,%2,%3};\n"
        : "+f"(d[0]), "+f"(d[1]), "+f"(d[2]), "+f"(d[3])
        : "r"(a[0]), "r"(a[1]), "r"(a[2]), "r"(a[3]), "r"(b[0]), "r"(b[1]));
}

// asrc: 0 -> (g_xh,g_xl); 1 -> (g_x1h,g_x1l); 2 -> (g_x2h,g_x2l)
// __launch_bounds__(256, 2): cap 128 regs -> 2 CTAs/SM (RF-limited otherwise)
__global__ __launch_bounds__(256, 2) void bgemm_kernel(int asrc, int wsel, int K)
{
    const __nv_bfloat16* Ah = (asrc == 0) ? g_xh : ((asrc == 1) ? g_x1h : g_x2h);
    const __nv_bfloat16* Al = (asrc == 0) ? g_xl : ((asrc == 1) ? g_x1l : g_x2l);
    const __nv_bfloat16* Bh = (wsel == 0) ? g_w1h : g_w2h;
    const __nv_bfloat16* Bl = (wsel == 0) ? g_w1l : g_w2l;
    float* C = g_xw;

    extern __shared__ char smem[];
    const uint32_t sbase = s2u(smem);

    const int tid = threadIdx.x;
    const int bm = blockIdx.y * GBM;
    const int bn = blockIdx.x * GBN;

    const int lane = tid & 31;
    const int warp = tid >> 5;
    const int wm = warp >> 1;
    const int wn = warp & 1;
    const int lrow = lane >> 2;
    const int lq   = lane & 3;
    const int la = lane & 15, ha = lane >> 4;

    // loader assignments
    const int a_row = tid >> 1;                 // 0..127
    const int a_c0  = (tid & 1) * 16;           // 0 or 16
    const bool a_ok = (bm + a_row) < NNODES;
    const int a_grow = a_ok ? (bm + a_row) : (NNODES - 1);
    const int b_k  = tid >> 3;                  // 0..31
    const int b_n0 = (tid & 7) * 16;            // 0..112

    float d[2][8][4];
#pragma unroll
    for (int i = 0; i < 2; i++)
#pragma unroll
        for (int j = 0; j < 8; j++)
#pragma unroll
            for (int r = 0; r < 4; r++) d[i][j][r] = 0.f;

    const int T = K / GBK;

    // tile loader
    auto load_tile = [&](int t, int s) {
        uint32_t st = sbase + s * STAGE;
        const __nv_bfloat16* pah = Ah + (size_t)a_grow * K + t * GBK + a_c0;
        const __nv_bfloat16* pal = Al + (size_t)a_grow * K + t * GBK + a_c0;
        uint32_t da = st + AH_OFF + (uint32_t)(a_row * AKP + a_c0) * 2;
        cp16(da,     pah,     a_ok);
        cp16(da + 16, pah + 8, a_ok);
        da = st + AL_OFF + (uint32_t)(a_row * AKP + a_c0) * 2;
        cp16(da,     pal,     a_ok);
        cp16(da + 16, pal + 8, a_ok);
        const __nv_bfloat16* pbh = Bh + (size_t)(t * GBK + b_k) * HID + bn + b_n0;
        const __nv_bfloat16* pbl = Bl + (size_t)(t * GBK + b_k) * HID + bn + b_n0;
        uint32_t db = st + BH_OFF + (uint32_t)(b_k * BNP + b_n0) * 2;
        cp16(db,     pbh,     true);
        cp16(db + 16, pbh + 8, true);
        db = st + BL_OFF + (uint32_t)(b_k * BNP + b_n0) * 2;
        cp16(db,     pbl,     true);
        cp16(db + 16, pbl + 8, true);
    };

    load_tile(0, 0);
    cp_commit();

    int buf = 0;
    for (int t = 0; t < T; t++) {
        cp_wait0();
        __syncthreads();
        if (t + 1 < T) { load_tile(t + 1, buf ^ 1); cp_commit(); }

        const uint32_t st = sbase + buf * STAGE;
        const uint32_t ash0 = st + AH_OFF;
        const uint32_t asl0 = st + AL_OFF;
        const uint32_t bsh0 = st + BH_OFF;
        const uint32_t bsl0 = st + BL_OFF;
#pragma unroll
        for (int ks = 0; ks < GBK; ks += 16) {
            unsigned ah[2][4], al[2][4];
#pragma unroll
            for (int fm = 0; fm < 2; fm++) {
                int m = wm * 32 + fm * 16 + la;
                int kc = ks + ha * 8;
                uint32_t off = (uint32_t)(m * AKP + kc) * 2;
                ldsm_x4(ah[fm], ash0 + off);
                ldsm_x4(al[fm], asl0 + off);
            }
#pragma unroll
            for (int fp = 0; fp < 4; fp++) {
                unsigned bh[4], bl[4];
                int kr = ks + la;
                int nc = wn * 64 + fp * 16 + ha * 8;
                uint32_t off = (uint32_t)(kr * BNP + nc) * 2;
                ldsm_x4_t(bh, bsh0 + off);
                ldsm_x4_t(bl, bsl0 + off);
#pragma unroll
                for (int fm = 0; fm < 2; fm++) {
#pragma unroll
                    for (int tt = 0; tt < 2; tt++) {
                        float* acc = d[fm][fp * 2 + tt];
                        mma_bf16(acc, ah[fm], &bh[tt * 2]);
                        mma_bf16(acc, ah[fm], &bl[tt * 2]);
                        mma_bf16(acc, al[fm], &bh[tt * 2]);
                    }
                }
            }
        }
        buf ^= 1;
    }

    // ---- epilogue ----
#pragma unroll
    for (int fm = 0; fm < 2; fm++) {
#pragma unroll
        for (int fn = 0; fn < 8; fn++) {
            int row = bm + wm * 32 + fm * 16 + lrow;
            int col = bn + wn * 64 + fn * 8 + 2 * lq;
            if (row < NNODES)
                *(float2*)&C[(size_t)row * HID + col] =
                    make_float2(d[fm][fn][0], d[fm][fn][1]);
            if (row + 8 < NNODES)
                *(float2*)&C[(size_t)(row + 8) * HID + col] =
                    make_float2(d[fm][fn][2], d[fm][fn][3]);
        }
    }
}

// ---------------- GCN aggregation + fused score + bf16 split out ----------------
__global__ __launch_bounds__(256) void agg_kernel(
    const float* __restrict__ bias, int out_sel,
    const float* __restrict__ pwseg, int layer, int write_split)
{
    const float* xw = g_xw;
    float* out = buf_select(out_sel);
    const int node = blockIdx.x;
    const int t = threadIdx.x;
    __shared__ int   s_src[CAP];
    __shared__ float s_nrm[CAP];
    __shared__ int   s_cnt;
    __shared__ float s_wsum[8];
    if (t == 0) { int c = g_cnt[node]; s_cnt = c < CAP ? c : CAP; }
    __syncthreads();
    const int cnt = s_cnt;
    if (t < cnt) {
        int e = g_eperm[node * CAP + t];
        s_src[t] = g_src[e];
        s_nrm[t] = g_norm[e];
    }
    __syncthreads();

    float d = g_deg[node];
    float acc = d * d * xw[(size_t)node * HID + t] + bias[t];
    int j = 0;
    for (; j + 4 <= cnt; j += 4) {
        float v0 = xw[(size_t)s_src[j + 0] * HID + t];
        float v1 = xw[(size_t)s_src[j + 1] * HID + t];
        float v2 = xw[(size_t)s_src[j + 2] * HID + t];
        float v3 = xw[(size_t)s_src[j + 3] * HID + t];
        acc += s_nrm[j + 0] * v0;
        acc += s_nrm[j + 1] * v1;
        acc += s_nrm[j + 2] * v2;
        acc += s_nrm[j + 3] * v3;
    }
    for (; j < cnt; j++)
        acc += s_nrm[j] * xw[(size_t)s_src[j] * HID + t];

    float v = fmaxf(acc, 0.f);
    out[(size_t)node * HID + t] = v;

    if (write_split) {
        __nv_bfloat16* oh = (out_sel == 1) ? g_x1h : g_x2h;
        __nv_bfloat16* ol = (out_sel == 1) ? g_x1l : g_x2l;
        __nv_bfloat16 h = __float2bfloat16(v);
        oh[(size_t)node * HID + t] = h;
        ol[(size_t)node * HID + t] = __float2bfloat16(v - __bfloat162float(h));
    }

    float p = v * pwseg[t];
#pragma unroll
    for (int o = 16; o > 0; o >>= 1) p += __shfl_xor_sync(0xffffffffu, p, o);
    if ((t & 31) == 0) s_wsum[t >> 5] = p;
    __syncthreads();
    if (t == 0) {
        float s = 0.f;
#pragma unroll
        for (int w = 0; w < 8; w++) s += s_wsum[w];
        g_sp[layer * NNODES + node] = s;
    }
}

// ---------------- scoring ----------------
__global__ void pwnorm_kernel(const float* __restrict__ pw) {
    __shared__ float red[256];
    float s = 0.f;
    for (int i = threadIdx.x; i < H3; i += 256) s += pw[i] * pw[i];
    red[threadIdx.x] = s;
    __syncthreads();
    for (int o = 128; o > 0; o >>= 1) {
        if (threadIdx.x < o) red[threadIdx.x] += red[threadIdx.x + o];
        __syncthreads();
    }
    if (threadIdx.x == 0) g_pwinv = rsqrtf(red[0]);
}

__global__ void scorefin_kernel() {
    int i = blockIdx.x * 256 + threadIdx.x;
    if (i >= NNODES) return;
    float dot = g_sp[i] + g_sp[NNODES + i] + g_sp[2 * NNODES + i];
    g_score[i] = 1.f / (1.f + expf(-dot * g_pwinv));
}

// ---------------- exact top-K threshold per graph ----------------
__global__ void radix_kernel() {
    const int g = blockIdx.x;
    const float* sc = g_score + g * NPG;
    __shared__ int hist[256];
    __shared__ unsigned s_prefix;
    __shared__ int s_remaining;
    if (threadIdx.x == 0) { s_prefix = 0u; s_remaining = KTOP; }
    __syncthreads();
    for (int pass = 3; pass >= 0; --pass) {
        hist[threadIdx.x] = 0;
        __syncthreads();
        unsigned prefix = s_prefix;
        int shift = pass * 8;
        for (int i = threadIdx.x; i < NPG; i += 256) {
            unsigned bits = __float_as_uint(sc[i]);
            bool match = (pass == 3) || ((bits >> (shift + 8)) == prefix);
            if (match) atomicAdd(&hist[(bits >> shift) & 255u], 1);
        }
        __syncthreads();
        if (threadIdx.x == 0) {
            int rem = s_remaining;
            unsigned p = s_prefix;
            for (int b = 255; b >= 0; --b) {
                if (hist[b] >= rem) { s_prefix = (p << 8) | (unsigned)b; break; }
                rem -= hist[b];
            }
            s_remaining = rem;
        }
        __syncthreads();
    }
    if (threadIdx.x == 0) { g_thr[g] = s_prefix; g_needeq[g] = s_remaining; }
}

// ---- stable tie resolution ----
__global__ void eqcnt_kernel() {
    const int ch = blockIdx.x % NCHUNK;
    const int g  = blockIdx.x / NCHUNK;
    const unsigned thr = g_thr[g];
    int i = ch * 256 + threadIdx.x;
    bool eq = (i < NPG) && (__float_as_uint(g_score[g * NPG + i]) == thr);
    unsigned bal = __ballot_sync(0xffffffffu, eq);
    __shared__ int wcnt[8];
    if ((threadIdx.x & 31) == 0) wcnt[threadIdx.x >> 5] = __popc(bal);
    __syncthreads();
    if (threadIdx.x == 0) {
        int s = 0;
#pragma unroll
        for (int w = 0; w < 8; w++) s += wcnt[w];
        g_eqcnt[g * NCHUNK + ch] = s;
    }
}

__global__ void eqscan_kernel() {
    const int g = blockIdx.x;
    if (threadIdx.x == 0) {
        int run = 0;
        for (int c = 0; c < NCHUNK; c++) {
            g_eqoff[g * NCHUNK + c] = run;
            run += g_eqcnt[g * NCHUNK + c];
        }
    }
}

__global__ void mark_kernel() {
    const int ch = blockIdx.x % NCHUNK;
    const int g  = blockIdx.x / NCHUNK;
    const unsigned thr = g_thr[g];
    const int need = g_needeq[g];
    int i = ch * 256 + threadIdx.x;
    float s = 0.f; unsigned bits = 0u;
    if (i < NPG) { s = g_score[g * NPG + i]; bits = __float_as_uint(s); }
    bool eq = (i < NPG) && (bits == thr);
    unsigned bal = __ballot_sync(0xffffffffu, eq);
    int lane = threadIdx.x & 31, warp = threadIdx.x >> 5;
    int lr = __popc(bal & ((1u << lane) - 1u));
    __shared__ int wcnt[8], woff[8];
    if (lane == 0) wcnt[warp] = __popc(bal);
    __syncthreads();
    if (threadIdx.x == 0) {
        int run = 0;
#pragma unroll
        for (int w = 0; w < 8; w++) { woff[w] = run; run += wcnt[w]; }
    }
    __syncthreads();
    if (i < NPG) {
        float out = 0.f;
        if (bits > thr) out = s;
        else if (eq) {
            int rank = g_eqoff[g * NCHUNK + ch] + woff[warp] + lr;
            if (rank < need) out = s;
        }
        g_sel[g * NPG + i] = out;
    }
}

// ---------------- readout, 2-stage ----------------
__global__ __launch_bounds__(256) void readout1_kernel() {
    const int sl = blockIdx.x % RSLICE;
    const int c  = (blockIdx.x / RSLICE) % 3;
    const int g  = blockIdx.x / (RSLICE * 3);
    const float* X = (c == 0) ? g_x1 : ((c == 1) ? g_x2 : g_x3);
    const int f = threadIdx.x;
    const float* sel = g_sel + g * NPG;
    const size_t rowbase = (size_t)g * NPG * HID;
    const int n0 = sl * (NPG / RSLICE), n1 = n0 + NPG / RSLICE;
    float sum0 = 0.f, sum1 = 0.f, mx = 0.f;
    for (int i = n0; i < n1; i += 2) {
        float v0 = sel[i]     * X[rowbase + (size_t)i * HID + f];
        float v1 = sel[i + 1] * X[rowbase + (size_t)(i + 1) * HID + f];
        sum0 += v0; sum1 += v1;
        mx = fmaxf(mx, fmaxf(v0, v1));
    }
    g_rsum[(size_t)blockIdx.x * HID + f] = sum0 + sum1;
    g_rmax[(size_t)blockIdx.x * HID + f] = mx;
}

__global__ __launch_bounds__(256) void readout2_kernel() {
    const int c = blockIdx.x % 3, g = blockIdx.x / 3;
    const int f = threadIdx.x;
    const int base = (g * 3 + c) * RSLICE;
    float sum = 0.f, mx = 0.f;
    for (int k = 0; k < RSLICE; k++) {
        sum += g_rsum[(size_t)(base + k) * HID + f];
        mx = fmaxf(mx, g_rmax[(size_t)(base + k) * HID + f]);
    }
    g_readout[g * 2 * H3 + c * HID + f]      = sum * (1.f / (float)KTOP);
    g_readout[g * 2 * H3 + H3 + c * HID + f] = mx;
}

// ---------------- final MLP ----------------
__global__ __launch_bounds__(256) void mlp_kernel(
    const float* __restrict__ lw1, const float* __restrict__ lb1,
    const float* __restrict__ lw2, const float* __restrict__ lb2,
    const float* __restrict__ lw3, const float* __restrict__ lb3,
    float* __restrict__ out)
{
    const int g = blockIdx.x, t = threadIdx.x;
    __shared__ float r[2 * H3];
    __shared__ float h1[HID];
    __shared__ float h2[HID / 2];
    for (int i = t; i < 2 * H3; i += 256) r[i] = g_readout[g * 2 * H3 + i];
    __syncthreads();
    {
        float a0 = 0.f, a1 = 0.f, a2 = 0.f, a3 = 0.f;
        for (int k = 0; k < 2 * H3; k += 4) {
            a0 += r[k + 0] * lw1[(size_t)(k + 0) * HID + t];
            a1 += r[k + 1] * lw1[(size_t)(k + 1) * HID + t];
            a2 += r[k + 2] * lw1[(size_t)(k + 2) * HID + t];
            a3 += r[k + 3] * lw1[(size_t)(k + 3) * HID + t];
        }
        h1[t] = fmaxf((a0 + a1) + (a2 + a3) + lb1[t], 0.f);
    }
    __syncthreads();
    if (t < 128) {
        float a0 = 0.f, a1 = 0.f;
        for (int k = 0; k < HID; k += 2) {
            a0 += h1[k + 0] * lw2[(size_t)(k + 0) * 128 + t];
            a1 += h1[k + 1] * lw2[(size_t)(k + 1) * 128 + t];
        }
        h2[t] = fmaxf(a0 + a1 + lb2[t], 0.f);
    }
    __syncthreads();
    if (t < 3) {
        float a = lb3[t];
        for (int k = 0; k < 128; k++) a += h2[k] * lw3[k * 3 + t];
        out[g * 3 + t] = a;
    }
}

// ---------------- launch ----------------
extern "C" void kernel_launch(void* const* d_in, const int* in_sizes, int n_in,
                              void* d_out, int out_size)
{
    int ix = -1, iei = -1, iea = -1, iW1 = -1, iW2 = -1, ipw = -1;
    int ilw1 = -1, ilw2 = -1, ilb2 = -1, ilw3 = -1, ilb3 = -1;
    int b256[3] = {-1, -1, -1};
    int nb = 0;
    for (int i = 0; i < n_in; i++) {
        switch (in_sizes[i]) {
            case 25600000: ix   = i; break;
            case 1600000:  iei  = i; break;
            case 800000:   iea  = i; break;
            case 131072:   iW1  = i; break;
            case 65536:    iW2  = i; break;
            case 768:      ipw  = i; break;
            case 393216:   ilw1 = i; break;
            case 32768:    ilw2 = i; break;
            case 128:      ilb2 = i; break;
            case 384:      ilw3 = i; break;
            case 3:        ilb3 = i; break;
            case 256:      if (nb < 3) b256[nb++] = i; break;
            default: break;
        }
    }

    const float* x   = (const float*)d_in[ix];
    const int*   ei  = (const int*)d_in[iei];
    const float* ea  = (const float*)d_in[iea];
    const float* W1  = (const float*)d_in[iW1];
    const float* b1  = (const float*)d_in[b256[0]];
    const float* W2  = (const float*)d_in[iW2];
    const float* b2  = (const float*)d_in[b256[1]];
    const float* pw  = (const float*)d_in[ipw];
    const float* lw1 = (const float*)d_in[ilw1];
    const float* lb1 = (const float*)d_in[b256[2]];
    const float* lw2 = (const float*)d_in[ilw2];
    const float* lb2 = (const float*)d_in[ilb2];
    const float* lw3 = (const float*)d_in[ilw3];
    const float* lb3 = (const float*)d_in[ilb3];
    float* out = (float*)d_out;

    static int smem_set = 0;
    if (!smem_set) {
        cudaFuncSetAttribute(bgemm_kernel,
                             cudaFuncAttributeMaxDynamicSharedMemorySize,
                             2 * STAGE);
        smem_set = 1;
    }

    const int nb_nodes = (NNODES + 255) / 256;
    const int nb_edges = (NEDGES + 255) / 256;
    dim3 gemm_grid(HID / GBN, (NNODES + GBM - 1) / GBM);

    // order chosen so launch #4 (ncu capture point) is the big GEMM
    splitw_kernel<<<(CIN * HID + 255) / 256, 256>>>(W1, CIN * HID, 0);      // 1
    splitx_kernel<<<(NNODES * CIN / 4 + 255) / 256, 256>>>(x);              // 2
    zero_kernel<<<nb_nodes, 256>>>();                                       // 3
    bgemm_kernel<<<gemm_grid, 256, 2 * STAGE>>>(0, 0, CIN);                 // 4
    splitw_kernel<<<(HID * HID + 255) / 256, 256>>>(W2, HID * HID, 1);      // 5
    fill_kernel<<<nb_edges, 256>>>(ei, ea);                                 // 6
    dinv_kernel<<<nb_nodes, 256>>>();                                       // 7
    norm_kernel<<<nb_edges, 256>>>(ei, ea);                                 // 8

    agg_kernel<<<NNODES, 256>>>(b1, 1, pw, 0, 1);                           // 9
    bgemm_kernel<<<gemm_grid, 256, 2 * STAGE>>>(1, 1, HID);                 // 10
    agg_kernel<<<NNODES, 256>>>(b2, 2, pw + HID, 1, 1);                     // 11
    bgemm_kernel<<<gemm_grid, 256, 2 * STAGE>>>(2, 1, HID);                 // 12
    agg_kernel<<<NNODES, 256>>>(b2, 3, pw + 2 * HID, 2, 0);                 // 13

    pwnorm_kernel<<<1, 256>>>(pw);
    scorefin_kernel<<<nb_nodes, 256>>>();
    radix_kernel<<<NGRAPH, 256>>>();
    eqcnt_kernel<<<NGRAPH * NCHUNK, 256>>>();
    eqscan_kernel<<<NGRAPH, 32>>>();
    mark_kernel<<<NGRAPH * NCHUNK, 256>>>();
    readout1_kernel<<<NGRAPH * 3 * RSLICE, 256>>>();
    readout2_kernel<<<NGRAPH * 3, 256>>>();
    mlp_kernel<<<NGRAPH, 256>>>(lw1, lb1, lw2, lb2, lw3, lb3, out);
}